// round 4
// baseline (speedup 1.0000x reference)
#include <cuda_runtime.h>
#include <cuda_bf16.h>
#include <cstdint>

#define USER_NUM 80000
#define ITEM_NUM 40000
#define NTOT     (USER_NUM + ITEM_NUM)   // 120000
#define EMB      64
#define NNZ      1200000
#define N_LAYERS 3

#define TOTAL_F  (NTOT * EMB)            // 7,680,000 floats
#define TOTAL_V4 (TOTAL_F / 4)           // 1,920,000 float4

// Scratch ping-pong buffers (allocation-free rule: __device__ globals)
__device__ float g_bufA[TOTAL_F];
__device__ float g_bufB[TOTAL_F];

// ---------------------------------------------------------------------------
// init: A = concat(user_emb, item_emb), B = 0
// ---------------------------------------------------------------------------
__global__ void init_kernel(const float4* __restrict__ user4,
                            const float4* __restrict__ item4) {
    int i = blockIdx.x * blockDim.x + threadIdx.x;
    if (i >= TOTAL_V4) return;
    float4* A4 = reinterpret_cast<float4*>(g_bufA);
    float4* B4 = reinterpret_cast<float4*>(g_bufB);
    const int user_v4 = USER_NUM * EMB / 4;   // 1,280,000
    float4 v;
    if (i < user_v4) v = user4[i];
    else             v = item4[i - user_v4];
    A4[i] = v;
    B4[i] = make_float4(0.f, 0.f, 0.f, 0.f);
}

// ---------------------------------------------------------------------------
// COO SpMM scatter: y[rows[e]] += vals[e] * x[cols[e]]
// dir==0 : x = g_bufA, y = g_bufB ;  dir==1 : x = g_bufB, y = g_bufA
// 16 threads per nonzero; each thread: one float4 gather + 4 scalar atomicAdd
// (ptxas emits RED.E.ADD.F32 — no return value used).
// ---------------------------------------------------------------------------
__global__ void spmm_kernel(const float* __restrict__ vals,
                            const int*   __restrict__ rows,
                            const int*   __restrict__ cols,
                            int dir) {
    long long t = (long long)blockIdx.x * blockDim.x + threadIdx.x;
    if (t >= (long long)NNZ * 16) return;
    int e = (int)(t >> 4);          // nonzero index
    int c = ((int)t & 15) * 4;      // element offset within the 64-wide row

    const float* x = dir ? g_bufB : g_bufA;
    float*       y = dir ? g_bufA : g_bufB;

    float v  = vals[e];
    int   r  = rows[e];
    int   cl = cols[e];

    const float4 xv = *reinterpret_cast<const float4*>(x + (size_t)cl * EMB + c);

    float* dst = y + (size_t)r * EMB + c;
    atomicAdd(dst + 0, v * xv.x);
    atomicAdd(dst + 1, v * xv.y);
    atomicAdd(dst + 2, v * xv.z);
    atomicAdd(dst + 3, v * xv.w);
}

// ---------------------------------------------------------------------------
// accumulate: out (+)= src * (1/3); optionally zero the buffer that becomes
// the next layer's scatter target.
// which==0 : src = g_bufB, zero g_bufA
// which==1 : src = g_bufA, zero g_bufB
// which==2 : src = g_bufB, zero nothing
// ---------------------------------------------------------------------------
__global__ void accum_kernel(float4* __restrict__ out4, int which, int first) {
    int i = blockIdx.x * blockDim.x + threadIdx.x;
    if (i >= TOTAL_V4) return;
    const float4* src4 = (which == 1) ? reinterpret_cast<const float4*>(g_bufA)
                                      : reinterpret_cast<const float4*>(g_bufB);
    float4* zero4 = nullptr;
    if (which == 0) zero4 = reinterpret_cast<float4*>(g_bufA);
    if (which == 1) zero4 = reinterpret_cast<float4*>(g_bufB);

    const float inv3 = 1.0f / 3.0f;
    float4 y = src4[i];
    float4 o;
    if (first) {
        o.x = y.x * inv3; o.y = y.y * inv3; o.z = y.z * inv3; o.w = y.w * inv3;
    } else {
        float4 a = out4[i];
        o.x = a.x + y.x * inv3; o.y = a.y + y.y * inv3;
        o.z = a.z + y.z * inv3; o.w = a.w + y.w * inv3;
    }
    out4[i] = o;
    if (zero4) zero4[i] = make_float4(0.f, 0.f, 0.f, 0.f);
}

// ---------------------------------------------------------------------------
// launch: nothing but kernel launches — trivially graph-capturable.
// ---------------------------------------------------------------------------
extern "C" void kernel_launch(void* const* d_in, const int* in_sizes, int n_in,
                              void* d_out, int out_size) {
    const float* user_emb = (const float*)d_in[0];
    const float* item_emb = (const float*)d_in[1];
    const float* adj_vals = (const float*)d_in[2];
    const int*   adj_rows = (const int*)d_in[3];
    const int*   adj_cols = (const int*)d_in[4];
    float4* out = (float4*)d_out;

    const int TB = 256;
    const int gridV4 = (TOTAL_V4 + TB - 1) / TB;
    const long long spmm_threads = (long long)NNZ * 16;
    const int gridS = (int)((spmm_threads + TB - 1) / TB);

    // A = ego, B = 0
    init_kernel<<<gridV4, TB>>>((const float4*)user_emb, (const float4*)item_emb);

    // Layer 0: spmm A->B ; out = B/3 ; zero A (next scatter target)
    spmm_kernel<<<gridS, TB>>>(adj_vals, adj_rows, adj_cols, 0);
    accum_kernel<<<gridV4, TB>>>(out, 0, 1);

    // Layer 1: spmm B->A ; out += A/3 ; zero B
    spmm_kernel<<<gridS, TB>>>(adj_vals, adj_rows, adj_cols, 1);
    accum_kernel<<<gridV4, TB>>>(out, 1, 0);

    // Layer 2: spmm A->B ; out += B/3
    spmm_kernel<<<gridS, TB>>>(adj_vals, adj_rows, adj_cols, 0);
    accum_kernel<<<gridV4, TB>>>(out, 2, 0);
}

// round 5
// speedup vs baseline: 1.9717x; 1.9717x over previous
#include <cuda_runtime.h>
#include <cuda_bf16.h>
#include <cstdint>

#define USER_NUM 80000
#define ITEM_NUM 40000
#define NTOT     (USER_NUM + ITEM_NUM)   // 120000
#define EMB      64
#define NNZ      1200000
#define N_LAYERS 3

#define TOTAL_F  (NTOT * EMB)            // 7,680,000 floats
#define TOTAL_V4 (TOTAL_F / 4)           // 1,920,000 float4

// Scratch ping-pong buffers (allocation-free rule: __device__ globals)
__device__ float g_bufA[TOTAL_F];
__device__ float g_bufB[TOTAL_F];

// ---------------------------------------------------------------------------
// init: A = concat(user_emb, item_emb), B = 0
// ---------------------------------------------------------------------------
__global__ void init_kernel(const float4* __restrict__ user4,
                            const float4* __restrict__ item4) {
    int i = blockIdx.x * blockDim.x + threadIdx.x;
    if (i >= TOTAL_V4) return;
    float4* A4 = reinterpret_cast<float4*>(g_bufA);
    float4* B4 = reinterpret_cast<float4*>(g_bufB);
    const int user_v4 = USER_NUM * EMB / 4;   // 1,280,000
    float4 v;
    if (i < user_v4) v = user4[i];
    else             v = item4[i - user_v4];
    A4[i] = v;
    B4[i] = make_float4(0.f, 0.f, 0.f, 0.f);
}

// ---------------------------------------------------------------------------
// COO SpMM scatter: y[rows[e]] += vals[e] * x[cols[e]]
// dir==0 : x = g_bufA, y = g_bufB ;  dir==1 : x = g_bufB, y = g_bufA
// 16 threads per nonzero; each thread: one float4 gather + ONE vector
// atomicAdd(float4*) (sm_90+ native intrinsic -> RED.ADD.v4 — 4x fewer
// LSU/LTS atomic ops than scalar).
// ---------------------------------------------------------------------------
__global__ void spmm_kernel(const float* __restrict__ vals,
                            const int*   __restrict__ rows,
                            const int*   __restrict__ cols,
                            int dir) {
    long long t = (long long)blockIdx.x * blockDim.x + threadIdx.x;
    if (t >= (long long)NNZ * 16) return;
    int e = (int)(t >> 4);          // nonzero index
    int c = ((int)t & 15) * 4;      // element offset within the 64-wide row

    const float* x = dir ? g_bufB : g_bufA;
    float*       y = dir ? g_bufA : g_bufB;

    float v  = vals[e];
    int   r  = rows[e];
    int   cl = cols[e];

    const float4 xv = *reinterpret_cast<const float4*>(x + (size_t)cl * EMB + c);
    float4 p;
    p.x = v * xv.x; p.y = v * xv.y; p.z = v * xv.z; p.w = v * xv.w;

    float* dst = y + (size_t)r * EMB + c;
#if __CUDA_ARCH__ >= 900
    atomicAdd(reinterpret_cast<float4*>(dst), p);
#else
    atomicAdd(dst + 0, p.x);
    atomicAdd(dst + 1, p.y);
    atomicAdd(dst + 2, p.z);
    atomicAdd(dst + 3, p.w);
#endif
}

// ---------------------------------------------------------------------------
// accumulate: out (+)= src * (1/3); optionally zero the buffer that becomes
// the next layer's scatter target.
// which==0 : src = g_bufB, zero g_bufA
// which==1 : src = g_bufA, zero g_bufB
// which==2 : src = g_bufB, zero nothing
// ---------------------------------------------------------------------------
__global__ void accum_kernel(float4* __restrict__ out4, int which, int first) {
    int i = blockIdx.x * blockDim.x + threadIdx.x;
    if (i >= TOTAL_V4) return;
    const float4* src4 = (which == 1) ? reinterpret_cast<const float4*>(g_bufA)
                                      : reinterpret_cast<const float4*>(g_bufB);
    float4* zero4 = nullptr;
    if (which == 0) zero4 = reinterpret_cast<float4*>(g_bufA);
    if (which == 1) zero4 = reinterpret_cast<float4*>(g_bufB);

    const float inv3 = 1.0f / 3.0f;
    float4 y = src4[i];
    float4 o;
    if (first) {
        o.x = y.x * inv3; o.y = y.y * inv3; o.z = y.z * inv3; o.w = y.w * inv3;
    } else {
        float4 a = out4[i];
        o.x = a.x + y.x * inv3; o.y = a.y + y.y * inv3;
        o.z = a.z + y.z * inv3; o.w = a.w + y.w * inv3;
    }
    out4[i] = o;
    if (zero4) zero4[i] = make_float4(0.f, 0.f, 0.f, 0.f);
}

// ---------------------------------------------------------------------------
// launch: nothing but kernel launches — trivially graph-capturable.
// ---------------------------------------------------------------------------
extern "C" void kernel_launch(void* const* d_in, const int* in_sizes, int n_in,
                              void* d_out, int out_size) {
    const float* user_emb = (const float*)d_in[0];
    const float* item_emb = (const float*)d_in[1];
    const float* adj_vals = (const float*)d_in[2];
    const int*   adj_rows = (const int*)d_in[3];
    const int*   adj_cols = (const int*)d_in[4];
    float4* out = (float4*)d_out;

    const int TB = 256;
    const int gridV4 = (TOTAL_V4 + TB - 1) / TB;
    const long long spmm_threads = (long long)NNZ * 16;
    const int gridS = (int)((spmm_threads + TB - 1) / TB);

    // A = ego, B = 0
    init_kernel<<<gridV4, TB>>>((const float4*)user_emb, (const float4*)item_emb);

    // Layer 0: spmm A->B ; out = B/3 ; zero A (next scatter target)
    spmm_kernel<<<gridS, TB>>>(adj_vals, adj_rows, adj_cols, 0);
    accum_kernel<<<gridV4, TB>>>(out, 0, 1);

    // Layer 1: spmm B->A ; out += A/3 ; zero B
    spmm_kernel<<<gridS, TB>>>(adj_vals, adj_rows, adj_cols, 1);
    accum_kernel<<<gridV4, TB>>>(out, 1, 0);

    // Layer 2: spmm A->B ; out += B/3
    spmm_kernel<<<gridS, TB>>>(adj_vals, adj_rows, adj_cols, 0);
    accum_kernel<<<gridV4, TB>>>(out, 2, 0);
}